// round 4
// baseline (speedup 1.0000x reference)
#include <cuda_runtime.h>
#include <math_constants.h>

#define B_   4
#define T_   2048
#define C_   1024
#define H_   16
#define HS_  64
#define NTOK (B_*T_)          // 8192

// Scratch (device globals: no allocations allowed)
__device__ float g_q[(size_t)NTOK * C_];
__device__ float g_k[(size_t)NTOK * C_];
__device__ float g_v[(size_t)NTOK * C_];
__device__ float g_att[(size_t)NTOK * C_];

// ---------------------------------------------------------------------------
// Core SGEMM NT tile body:  C[m,n] = sum_k A[m,k] * B[n,k] (+bias)
// A: MxK row-major, B: NxK row-major, C: MxN row-major.
// 128x128 tile, BK=16, 256 threads, 8x8 per-thread register block.
// Software-pipelined: next-tile LDGs issue before the compute phase so their
// latency hides under ~1024 FFMAs per thread per k-tile.
// ---------------------------------------------------------------------------
__device__ __forceinline__ void sgemm_nt_tile(
    const float* __restrict__ A, const float* __restrict__ Bm,
    const float* __restrict__ bias, float* __restrict__ C,
    int N, int K, int bm, int bn)
{
    __shared__ float As[16][128];
    __shared__ float Bs[16][128];

    const int tid = threadIdx.x;
    const int tx  = tid & 15;     // 0..15
    const int ty  = tid >> 4;     // 0..15

    const int lr = tid >> 1;          // row within tile, 0..127
    const int lk = (tid & 1) << 3;    // 0 or 8

    const float* Ap = A  + (size_t)(bm + lr) * K + lk;
    const float* Bp = Bm + (size_t)(bn + lr) * K + lk;

    float acc[8][8];
    #pragma unroll
    for (int i = 0; i < 8; i++)
        #pragma unroll
        for (int j = 0; j < 8; j++) acc[i][j] = 0.f;

    // prologue: prefetch tile 0 into registers
    float4 a0 = *(const float4*)(Ap);
    float4 a1 = *(const float4*)(Ap + 4);
    float4 b0 = *(const float4*)(Bp);
    float4 b1 = *(const float4*)(Bp + 4);

    for (int k0 = 0; k0 < K; k0 += 16) {
        __syncthreads();   // previous compute-phase readers done
        As[lk+0][lr] = a0.x; As[lk+1][lr] = a0.y; As[lk+2][lr] = a0.z; As[lk+3][lr] = a0.w;
        As[lk+4][lr] = a1.x; As[lk+5][lr] = a1.y; As[lk+6][lr] = a1.z; As[lk+7][lr] = a1.w;
        Bs[lk+0][lr] = b0.x; Bs[lk+1][lr] = b0.y; Bs[lk+2][lr] = b0.z; Bs[lk+3][lr] = b0.w;
        Bs[lk+4][lr] = b1.x; Bs[lk+5][lr] = b1.y; Bs[lk+6][lr] = b1.z; Bs[lk+7][lr] = b1.w;
        __syncthreads();

        // issue next-tile global loads BEFORE compute so LDG latency overlaps
        int kn = k0 + 16;
        if (kn < K) {
            a0 = *(const float4*)(Ap + kn);
            a1 = *(const float4*)(Ap + kn + 4);
            b0 = *(const float4*)(Bp + kn);
            b1 = *(const float4*)(Bp + kn + 4);
        }

        #pragma unroll
        for (int kk = 0; kk < 16; kk++) {
            float a[8], b[8];
            *(float4*)(a)     = *(const float4*)(&As[kk][ty*4]);
            *(float4*)(a + 4) = *(const float4*)(&As[kk][ty*4 + 64]);
            *(float4*)(b)     = *(const float4*)(&Bs[kk][tx*4]);
            *(float4*)(b + 4) = *(const float4*)(&Bs[kk][tx*4 + 64]);
            #pragma unroll
            for (int i = 0; i < 8; i++)
                #pragma unroll
                for (int j = 0; j < 8; j++)
                    acc[i][j] += a[i] * b[j];
        }
    }

    float4 bv0 = make_float4(0.f, 0.f, 0.f, 0.f);
    float4 bv1 = make_float4(0.f, 0.f, 0.f, 0.f);
    if (bias != nullptr) {
        bv0 = *(const float4*)(bias + bn + tx*4);
        bv1 = *(const float4*)(bias + bn + 64 + tx*4);
    }

    #pragma unroll
    for (int i = 0; i < 8; i++) {
        int row = bm + ty*4 + (i & 3) + ((i >> 2) << 6);
        float4 r0, r1;
        r0.x = acc[i][0] + bv0.x; r0.y = acc[i][1] + bv0.y;
        r0.z = acc[i][2] + bv0.z; r0.w = acc[i][3] + bv0.w;
        r1.x = acc[i][4] + bv1.x; r1.y = acc[i][5] + bv1.y;
        r1.z = acc[i][6] + bv1.z; r1.w = acc[i][7] + bv1.w;
        *(float4*)(C + (size_t)row * N + bn + tx*4)      = r0;
        *(float4*)(C + (size_t)row * N + bn + 64 + tx*4) = r1;
    }
}

// Fused QKV: blockIdx.z in {0,1,2} selects the weight matrix & destination.
// Single launch (1536 CTAs) packs waves better than 3x512 and keeps x tiles
// + weight tiles hot in L2 across z-slices.
__global__ __launch_bounds__(256) void qkv_kernel(
    const float* __restrict__ x,
    const float* __restrict__ Wq, const float* __restrict__ Wk,
    const float* __restrict__ Wv,
    float* __restrict__ q, float* __restrict__ k, float* __restrict__ v)
{
    const int z = blockIdx.z;
    const float* W = (z == 0) ? Wq : (z == 1) ? Wk : Wv;
    float*       O = (z == 0) ? q  : (z == 1) ? k  : v;
    sgemm_nt_tile(x, W, nullptr, O, C_, C_,
                  blockIdx.y * 128, blockIdx.x * 128);
}

// Output projection (+bias)
__global__ __launch_bounds__(256) void proj_kernel(
    const float* __restrict__ A, const float* __restrict__ W,
    const float* __restrict__ bias, float* __restrict__ C)
{
    sgemm_nt_tile(A, W, bias, C, C_, C_,
                  blockIdx.y * 128, blockIdx.x * 128);
}

// ---------------------------------------------------------------------------
// Causal flash attention, fp32.
// Layouts: Q/K/V/O all [token n = b*T+t, channel c = h*HS+d] (row stride C_).
// Block: 128 threads, BM=128 query rows (1 row/thread), BN=64 key tile.
// Scores s[64] live in registers (j-loops fully unrolled); output accumulator
// lives in padded shared. K-tile reads are warp-broadcast LDS (conflict-free).
// The reference's x8 score scale (sqrt(HS), repo bug reproduced) is folded
// into the Q-tile load. Heavy CTAs (large qblk) launch first (LPT schedule).
// ---------------------------------------------------------------------------
#define ABM 128
#define ABN 64
#define QS  68   // padded fp32 row stride, float4-aligned
#define ATT_SMEM_BYTES ((ABM*QS*2 + ABN*QS*2) * 4)   // 104448

__global__ __launch_bounds__(128) void attn_kernel(
    const float* __restrict__ Q, const float* __restrict__ K,
    const float* __restrict__ V, float* __restrict__ O)
{
    extern __shared__ float smf[];
    float* q_sh = smf;                  // ABM x QS
    float* o_sh = q_sh + ABM*QS;        // ABM x QS
    float* k_sh = o_sh + ABM*QS;        // ABN x QS
    float* v_sh = k_sh + ABN*QS;        // ABN x QS

    const int bh   = blockIdx.y;
    const int b    = bh >> 4;
    const int h    = bh & 15;
    const int qblk = gridDim.x - 1 - blockIdx.x;   // LPT: heavy tiles first
    const int row  = threadIdx.x;            // 0..127
    const int qr   = qblk*ABM + row;         // global query index
    const size_t base = (size_t)b * T_ * C_ + (size_t)h * HS_;

    // Load Q tile (coalesced 256B rows), folding in the x8 score scale
    for (int idx = threadIdx.x; idx < ABM*HS_/4; idx += 128) {
        int r  = idx >> 4;
        int d4 = (idx & 15) << 2;
        float4 qv = *(const float4*)(Q + base + (size_t)(qblk*ABM + r) * C_ + d4);
        qv.x *= 8.0f; qv.y *= 8.0f; qv.z *= 8.0f; qv.w *= 8.0f;
        *(float4*)&q_sh[r*QS + d4] = qv;
    }
    #pragma unroll
    for (int d = 0; d < HS_; d++) o_sh[row*QS + d] = 0.f;
    __syncthreads();

    float m = -CUDART_INF_F;
    float l = 0.f;
    const int ntiles = 2*qblk + 2;           // key tiles 0 .. 2*qblk+1

    for (int jt = 0; jt < ntiles; jt++) {
        __syncthreads();   // previous tile's readers done before overwrite
        for (int idx = threadIdx.x; idx < ABN*HS_/4; idx += 128) {
            int r  = idx >> 4;
            int d4 = (idx & 15) << 2;
            size_t g = base + (size_t)(jt*ABN + r) * C_ + d4;
            *(float4*)&k_sh[r*QS + d4] = *(const float4*)(K + g);
            *(float4*)&v_sh[r*QS + d4] = *(const float4*)(V + g);
        }
        __syncthreads();

        // S = q_row . K^T   (s[j] in registers, j fully unrolled;
        //                    k_sh reads are warp-wide broadcasts)
        float s[ABN];
        #pragma unroll
        for (int j = 0; j < ABN; j++) s[j] = 0.f;

        const float* qrow = &q_sh[row*QS];
        #pragma unroll 1
        for (int d = 0; d < HS_; d += 4) {
            float4 qv = *(const float4*)(qrow + d);
            #pragma unroll
            for (int j = 0; j < ABN; j++) {
                float4 kv = *(const float4*)&k_sh[j*QS + d];
                s[j] += qv.x*kv.x + qv.y*kv.y + qv.z*kv.z + qv.w*kv.w;
            }
        }

        // causal mask + row max (scale already folded into Q)
        const int kbase = jt*ABN;
        float smax = -CUDART_INF_F;
        #pragma unroll
        for (int j = 0; j < ABN; j++) {
            float sj = (kbase + j > qr) ? -CUDART_INF_F : s[j];
            s[j] = sj;
            smax = fmaxf(smax, sj);
        }

        float mnew = fmaxf(m, smax);
        float corr = (m == -CUDART_INF_F) ? 0.f : __expf(m - mnew);
        float psum = 0.f;
        #pragma unroll
        for (int j = 0; j < ABN; j++) {
            float p = (s[j] == -CUDART_INF_F) ? 0.f : __expf(s[j] - mnew);
            s[j] = p;
            psum += p;
        }
        l = l * corr + psum;
        m = mnew;

        // O += P . V  (accumulator in shared, correction folded into load)
        float* orow = &o_sh[row*QS];
        #pragma unroll 1
        for (int d = 0; d < HS_; d += 4) {
            float4 acc = *(float4*)(orow + d);
            acc.x *= corr; acc.y *= corr; acc.z *= corr; acc.w *= corr;
            #pragma unroll
            for (int j = 0; j < ABN; j++) {
                float4 vv = *(const float4*)&v_sh[j*QS + d];
                acc.x += s[j]*vv.x; acc.y += s[j]*vv.y;
                acc.z += s[j]*vv.z; acc.w += s[j]*vv.w;
            }
            *(float4*)(orow + d) = acc;
        }
    }

    // epilogue: normalize and store
    const float inv = 1.0f / l;
    const float* orow = &o_sh[row*QS];
    #pragma unroll 1
    for (int d = 0; d < HS_; d += 4) {
        float4 acc = *(const float4*)(orow + d);
        acc.x *= inv; acc.y *= inv; acc.z *= inv; acc.w *= inv;
        *(float4*)(O + base + (size_t)qr * C_ + d) = acc;
    }
}

// ---------------------------------------------------------------------------
// Host launcher. Inputs (metadata order): x, Wq, Wk, Wv, Wo, bo. Output fp32.
// ---------------------------------------------------------------------------
extern "C" void kernel_launch(void* const* d_in, const int* in_sizes, int n_in,
                              void* d_out, int out_size)
{
    const float* x  = (const float*)d_in[0];
    const float* Wq = (const float*)d_in[1];
    const float* Wk = (const float*)d_in[2];
    const float* Wv = (const float*)d_in[3];
    const float* Wo = (const float*)d_in[4];
    const float* bo = (const float*)d_in[5];
    float* out = (float*)d_out;

    float *q, *k, *v, *att;
    cudaGetSymbolAddress((void**)&q,   g_q);
    cudaGetSymbolAddress((void**)&k,   g_k);
    cudaGetSymbolAddress((void**)&v,   g_v);
    cudaGetSymbolAddress((void**)&att, g_att);

    cudaFuncSetAttribute(attn_kernel,
                         cudaFuncAttributeMaxDynamicSharedMemorySize,
                         ATT_SMEM_BYTES);

    // Fused QKV projections: grid (8, 64, 3)
    qkv_kernel<<<dim3(C_/128, NTOK/128, 3), 256>>>(x, Wq, Wk, Wv, q, k, v);

    // Causal attention -> att [token, h*HS+d] (= concat-heads layout)
    attn_kernel<<<dim3(T_/ABM, B_*H_), 128, ATT_SMEM_BYTES>>>(q, k, v, att);

    // Output projection + bias
    proj_kernel<<<dim3(C_/128, NTOK/128), 256>>>(att, Wo, bo, out);
}

// round 12
// speedup vs baseline: 1.0688x; 1.0688x over previous
#include <cuda_runtime.h>
#include <math_constants.h>

#define B_   4
#define T_   2048
#define C_   1024
#define H_   16
#define HS_  64
#define NTOK (B_*T_)          // 8192

typedef unsigned long long ull;

// packed f32x2 helpers (sm_100+: fma.rn.f32x2)
#define FMA2(d, a, b, c) \
    asm("fma.rn.f32x2 %0, %1, %2, %3;" : "=l"(d) : "l"(a), "l"(b), "l"(c))
#define ADD2(d, a, b) \
    asm("add.rn.f32x2 %0, %1, %2;" : "=l"(d) : "l"(a), "l"(b))
#define DUP2(d, f) \
    asm("mov.b64 %0, {%1, %1};" : "=l"(d) : "r"(__float_as_uint(f)))
#define PACK2(d, lo, hi) \
    asm("mov.b64 %0, {%1, %2};" : "=l"(d) : "r"(__float_as_uint(lo)), "r"(__float_as_uint(hi)))
#define UNPACK2(lo, hi, v) do { unsigned _ulo, _uhi; \
    asm("mov.b64 {%0, %1}, %2;" : "=r"(_ulo), "=r"(_uhi) : "l"(v)); \
    lo = __uint_as_float(_ulo); hi = __uint_as_float(_uhi); } while (0)

// Scratch (device globals: no allocations allowed)
__device__ float g_q[(size_t)NTOK * C_];
__device__ float g_k[(size_t)NTOK * C_];
__device__ float g_v[(size_t)NTOK * C_];
__device__ float g_att[(size_t)NTOK * C_];

// ---------------------------------------------------------------------------
// Core SGEMM NT tile body:  C[m,n] = sum_k A[m,k] * B[n,k] (+bias)
// 128x128 tile, BK=16, 256 threads, 8x8 per-thread block, f32x2 packed FMAs.
// ---------------------------------------------------------------------------
__device__ __forceinline__ void sgemm_nt_tile(
    const float* __restrict__ A, const float* __restrict__ Bm,
    const float* __restrict__ bias, float* __restrict__ C,
    int N, int K, int bm, int bn)
{
    __shared__ float As[16][128];
    __shared__ float Bs[16][128];

    const int tid = threadIdx.x;
    const int tx  = tid & 15;     // 0..15
    const int ty  = tid >> 4;     // 0..15

    const int lr = tid >> 1;          // row within tile, 0..127
    const int lk = (tid & 1) << 3;    // 0 or 8

    const float* Ap = A  + (size_t)(bm + lr) * K + lk;
    const float* Bp = Bm + (size_t)(bn + lr) * K + lk;

    ull acc2[8][4];
    #pragma unroll
    for (int i = 0; i < 8; i++)
        #pragma unroll
        for (int j = 0; j < 4; j++) acc2[i][j] = 0ull;

    // prologue: prefetch tile 0 into registers
    float4 a0 = *(const float4*)(Ap);
    float4 a1 = *(const float4*)(Ap + 4);
    float4 b0 = *(const float4*)(Bp);
    float4 b1 = *(const float4*)(Bp + 4);

    for (int k0 = 0; k0 < K; k0 += 16) {
        __syncthreads();
        As[lk+0][lr] = a0.x; As[lk+1][lr] = a0.y; As[lk+2][lr] = a0.z; As[lk+3][lr] = a0.w;
        As[lk+4][lr] = a1.x; As[lk+5][lr] = a1.y; As[lk+6][lr] = a1.z; As[lk+7][lr] = a1.w;
        Bs[lk+0][lr] = b0.x; Bs[lk+1][lr] = b0.y; Bs[lk+2][lr] = b0.z; Bs[lk+3][lr] = b0.w;
        Bs[lk+4][lr] = b1.x; Bs[lk+5][lr] = b1.y; Bs[lk+6][lr] = b1.z; Bs[lk+7][lr] = b1.w;
        __syncthreads();

        // next-tile global loads issued before compute (latency overlap)
        int kn = k0 + 16;
        if (kn < K) {
            a0 = *(const float4*)(Ap + kn);
            a1 = *(const float4*)(Ap + kn + 4);
            b0 = *(const float4*)(Bp + kn);
            b1 = *(const float4*)(Bp + kn + 4);
        }

        #pragma unroll
        for (int kk = 0; kk < 16; kk++) {
            float a[8];
            *(float4*)(a)     = *(const float4*)(&As[kk][ty*4]);
            *(float4*)(a + 4) = *(const float4*)(&As[kk][ty*4 + 64]);
            ulonglong2 bb0 = *(const ulonglong2*)(&Bs[kk][tx*4]);
            ulonglong2 bb1 = *(const ulonglong2*)(&Bs[kk][tx*4 + 64]);
            ull da[8];
            #pragma unroll
            for (int i = 0; i < 8; i++) DUP2(da[i], a[i]);
            #pragma unroll
            for (int i = 0; i < 8; i++) {
                FMA2(acc2[i][0], da[i], bb0.x, acc2[i][0]);
                FMA2(acc2[i][1], da[i], bb0.y, acc2[i][1]);
                FMA2(acc2[i][2], da[i], bb1.x, acc2[i][2]);
                FMA2(acc2[i][3], da[i], bb1.y, acc2[i][3]);
            }
        }
    }

    // unpack accumulators
    float acc[8][8];
    #pragma unroll
    for (int i = 0; i < 8; i++)
        #pragma unroll
        for (int jp = 0; jp < 4; jp++)
            UNPACK2(acc[i][2*jp], acc[i][2*jp+1], acc2[i][jp]);

    float4 bv0 = make_float4(0.f, 0.f, 0.f, 0.f);
    float4 bv1 = make_float4(0.f, 0.f, 0.f, 0.f);
    if (bias != nullptr) {
        bv0 = *(const float4*)(bias + bn + tx*4);
        bv1 = *(const float4*)(bias + bn + 64 + tx*4);
    }

    #pragma unroll
    for (int i = 0; i < 8; i++) {
        int row = bm + ty*4 + (i & 3) + ((i >> 2) << 6);
        float4 r0, r1;
        r0.x = acc[i][0] + bv0.x; r0.y = acc[i][1] + bv0.y;
        r0.z = acc[i][2] + bv0.z; r0.w = acc[i][3] + bv0.w;
        r1.x = acc[i][4] + bv1.x; r1.y = acc[i][5] + bv1.y;
        r1.z = acc[i][6] + bv1.z; r1.w = acc[i][7] + bv1.w;
        *(float4*)(C + (size_t)row * N + bn + tx*4)      = r0;
        *(float4*)(C + (size_t)row * N + bn + 64 + tx*4) = r1;
    }
}

__global__ __launch_bounds__(256, 2) void qkv_kernel(
    const float* __restrict__ x,
    const float* __restrict__ Wq, const float* __restrict__ Wk,
    const float* __restrict__ Wv,
    float* __restrict__ q, float* __restrict__ k, float* __restrict__ v)
{
    const int z = blockIdx.z;
    const float* W = (z == 0) ? Wq : (z == 1) ? Wk : Wv;
    float*       O = (z == 0) ? q  : (z == 1) ? k  : v;
    sgemm_nt_tile(x, W, nullptr, O, C_, C_,
                  blockIdx.y * 128, blockIdx.x * 128);
}

__global__ __launch_bounds__(256, 2) void proj_kernel(
    const float* __restrict__ A, const float* __restrict__ W,
    const float* __restrict__ bias, float* __restrict__ C)
{
    sgemm_nt_tile(A, W, bias, C, C_, C_,
                  blockIdx.y * 128, blockIdx.x * 128);
}

// ---------------------------------------------------------------------------
// Causal flash attention, fp32, f32x2-packed inner loops.
// BM=128 (1 query row/thread, 128 threads), BN=64 keys/tile.
// Scores packed as 32 key-pairs in registers. K and V tiles stored TRANSPOSED
// ([d][j], j contiguous) so one 16B broadcast LDS feeds two packed FMAs.
// Q stored transposed ([d][row]) -> lane-consecutive conflict-free reads.
// O accumulator in shared, stride 65 (odd) -> conflict-free scalar access.
// x8 scale (sqrt(HS), repo bug reproduced) folded into Q load. LPT CTA order.
// ---------------------------------------------------------------------------
#define ABM 128
#define ABN 64
#define QTS 129   // qT stride (scalar access)
#define OS_ 65    // o_sh stride (odd -> conflict-free scalar access)
#define KTS 68    // kT/vT stride (rows 16B-aligned: 68*4=272)
// floats: qT 64*129=8256, oS 128*65=8320, kT 64*68=4352, vT 4352 -> 25280
#define ATT_SMEM_BYTES (25280 * 4)

__global__ __launch_bounds__(128) void attn_kernel(
    const float* __restrict__ Q, const float* __restrict__ K,
    const float* __restrict__ V, float* __restrict__ O)
{
    extern __shared__ float smf[];
    float* qT = smf;                   // [64][QTS]
    float* oS = qT + HS_*QTS;          // [128][OS_]
    float* kT = oS + ABM*OS_;          // [64][KTS]
    float* vT = kT + HS_*KTS;          // [64][KTS]

    const int bh   = blockIdx.y;
    const int b    = bh >> 4;
    const int h    = bh & 15;
    const int qblk = gridDim.x - 1 - blockIdx.x;   // LPT: heavy tiles first
    const int row  = threadIdx.x;                  // 0..127
    const int qr   = qblk*ABM + row;
    const size_t base = (size_t)b * T_ * C_ + (size_t)h * HS_;

    // Load Q tile -> transposed qT, folding in the x8 score scale
    for (int idx = threadIdx.x; idx < ABM*HS_/4; idx += 128) {
        int r  = idx >> 4;
        int d4 = (idx & 15) << 2;
        float4 qv = *(const float4*)(Q + base + (size_t)(qblk*ABM + r) * C_ + d4);
        qT[(d4+0)*QTS + r] = qv.x * 8.0f;
        qT[(d4+1)*QTS + r] = qv.y * 8.0f;
        qT[(d4+2)*QTS + r] = qv.z * 8.0f;
        qT[(d4+3)*QTS + r] = qv.w * 8.0f;
    }
    #pragma unroll
    for (int d = 0; d < HS_; d++) oS[row*OS_ + d] = 0.f;
    __syncthreads();

    float m = -CUDART_INF_F;
    float l = 0.f;
    const int ntiles = 2*qblk + 2;

    for (int jt = 0; jt < ntiles; jt++) {
        __syncthreads();   // previous tile's readers done before overwrite
        for (int idx = threadIdx.x; idx < ABN*HS_/4; idx += 128) {
            int r  = idx >> 4;           // key row 0..63
            int d4 = (idx & 15) << 2;
            size_t g = base + (size_t)(jt*ABN + r) * C_ + d4;
            float4 kk4 = *(const float4*)(K + g);
            float4 vv4 = *(const float4*)(V + g);
            kT[(d4+0)*KTS + r] = kk4.x; kT[(d4+1)*KTS + r] = kk4.y;
            kT[(d4+2)*KTS + r] = kk4.z; kT[(d4+3)*KTS + r] = kk4.w;
            vT[(d4+0)*KTS + r] = vv4.x; vT[(d4+1)*KTS + r] = vv4.y;
            vT[(d4+2)*KTS + r] = vv4.z; vT[(d4+3)*KTS + r] = vv4.w;
        }
        __syncthreads();

        // ---- S = q_row . K^T, packed over key pairs ----
        ull s2[ABN/2];
        #pragma unroll
        for (int j2 = 0; j2 < ABN/2; j2++) s2[j2] = 0ull;

        for (int d = 0; d < HS_; d++) {
            float qd = qT[d*QTS + row];
            ull q2; DUP2(q2, qd);
            const ulonglong2* krow = (const ulonglong2*)(kT + d*KTS);
            #pragma unroll
            for (int j4 = 0; j4 < 16; j4++) {
                ulonglong2 kk = krow[j4];
                FMA2(s2[2*j4+0], q2, kk.x, s2[2*j4+0]);
                FMA2(s2[2*j4+1], q2, kk.y, s2[2*j4+1]);
            }
        }

        // ---- causal mask + row max ----
        const int kbase = jt*ABN;
        float smax = -CUDART_INF_F;
        #pragma unroll
        for (int j2 = 0; j2 < ABN/2; j2++) {
            float f0, f1; UNPACK2(f0, f1, s2[j2]);
            f0 = (kbase + 2*j2     > qr) ? -CUDART_INF_F : f0;
            f1 = (kbase + 2*j2 + 1 > qr) ? -CUDART_INF_F : f1;
            PACK2(s2[j2], f0, f1);
            smax = fmaxf(smax, fmaxf(f0, f1));
        }

        float mnew = fmaxf(m, smax);
        float corr = (m == -CUDART_INF_F) ? 0.f : __expf(m - mnew);
        float psum = 0.f;
        #pragma unroll
        for (int j2 = 0; j2 < ABN/2; j2++) {
            float f0, f1; UNPACK2(f0, f1, s2[j2]);
            float p0 = (f0 == -CUDART_INF_F) ? 0.f : __expf(f0 - mnew);
            float p1 = (f1 == -CUDART_INF_F) ? 0.f : __expf(f1 - mnew);
            psum += p0 + p1;
            PACK2(s2[j2], p0, p1);
        }
        l = l * corr + psum;
        m = mnew;

        // ---- O += P . V, packed key-pairs, horizontal-add into shared O ----
        for (int d = 0; d < HS_; d++) {
            const ulonglong2* vrow = (const ulonglong2*)(vT + d*KTS);
            ull a0 = 0ull, a1 = 0ull, a2 = 0ull, a3 = 0ull;
            #pragma unroll
            for (int j4 = 0; j4 < 16; j4 += 2) {
                ulonglong2 v0 = vrow[j4];
                ulonglong2 v1 = vrow[j4+1];
                FMA2(a0, s2[2*j4+0], v0.x, a0);
                FMA2(a1, s2[2*j4+1], v0.y, a1);
                FMA2(a2, s2[2*j4+2], v1.x, a2);
                FMA2(a3, s2[2*j4+3], v1.y, a3);
            }
            ull t01, t23, t;
            ADD2(t01, a0, a1);
            ADD2(t23, a2, a3);
            ADD2(t, t01, t23);
            float lo, hi; UNPACK2(lo, hi, t);
            oS[row*OS_ + d] = corr * oS[row*OS_ + d] + (lo + hi);
        }
    }

    // epilogue: normalize and store
    const float inv = 1.0f / l;
    #pragma unroll
    for (int d = 0; d < HS_; d += 4) {
        float4 acc;
        acc.x = oS[row*OS_ + d+0] * inv;
        acc.y = oS[row*OS_ + d+1] * inv;
        acc.z = oS[row*OS_ + d+2] * inv;
        acc.w = oS[row*OS_ + d+3] * inv;
        *(float4*)(O + base + (size_t)qr * C_ + d) = acc;
    }
}

// ---------------------------------------------------------------------------
// Host launcher. Inputs (metadata order): x, Wq, Wk, Wv, Wo, bo. Output fp32.
// ---------------------------------------------------------------------------
extern "C" void kernel_launch(void* const* d_in, const int* in_sizes, int n_in,
                              void* d_out, int out_size)
{
    const float* x  = (const float*)d_in[0];
    const float* Wq = (const float*)d_in[1];
    const float* Wk = (const float*)d_in[2];
    const float* Wv = (const float*)d_in[3];
    const float* Wo = (const float*)d_in[4];
    const float* bo = (const float*)d_in[5];
    float* out = (float*)d_out;

    float *q, *k, *v, *att;
    cudaGetSymbolAddress((void**)&q,   g_q);
    cudaGetSymbolAddress((void**)&k,   g_k);
    cudaGetSymbolAddress((void**)&v,   g_v);
    cudaGetSymbolAddress((void**)&att, g_att);

    cudaFuncSetAttribute(attn_kernel,
                         cudaFuncAttributeMaxDynamicSharedMemorySize,
                         ATT_SMEM_BYTES);

    // Fused QKV projections: grid (8, 64, 3)
    qkv_kernel<<<dim3(C_/128, NTOK/128, 3), 256>>>(x, Wq, Wk, Wv, q, k, v);

    // Causal attention -> att [token, h*HS+d] (= concat-heads layout)
    attn_kernel<<<dim3(T_/ABM, B_*H_), 128, ATT_SMEM_BYTES>>>(q, k, v, att);

    // Output projection + bias
    proj_kernel<<<dim3(C_/128, NTOK/128), 256>>>(att, Wo, bo, out);
}